// round 4
// baseline (speedup 1.0000x reference)
#include <cuda_runtime.h>
#include <cstdint>

// ============================================================================
// QKV projection as one tf32 mma.sync GEMM (baseline PTX — no tcgen05, which
// this toolchain's .target sm_103 rejects):
//   C[16384, 12288] = A[16384,4096] @ B[12288,4096]^T
// A = hidden_states (row-major), B = qkv_proj (row-major), RoPE = identity.
// Output: 3 column sections of C -> q|k|v concatenated fp32 regions.
// ============================================================================

static constexpr int MDIM = 16384;
static constexpr int NDIM = 12288;
static constexpr int KDIM = 4096;

static constexpr int BM = 256;
static constexpr int BN = 128;
static constexpr int BK = 32;                  // 32 fp32 = 128 B row
static constexpr int KTILES = KDIM / BK;       // 128
static constexpr int STAGES = 3;
static constexpr int A_BYTES = BM * BK * 4;    // 32 KB
static constexpr int B_BYTES = BN * BK * 4;    // 16 KB
static constexpr int STAGE_BYTES = A_BYTES + B_BYTES;      // 48 KB
static constexpr int SMEM_TOTAL = STAGES * STAGE_BYTES;    // 144 KB
static constexpr int M_TILES = MDIM / BM;      // 64
static constexpr int N_TILES = NDIM / BN;      // 96
static constexpr int PANEL_M = 8;              // L2 rasterization panel
static constexpr int NTHREADS = 512;

__device__ __forceinline__ uint32_t smem_u32(const void* p) {
    uint32_t a;
    asm("{ .reg .u64 t; cvta.to.shared.u64 t, %1; cvt.u32.u64 %0, t; }"
        : "=r"(a) : "l"(p));
    return a;
}

__device__ __forceinline__ void cpa16(uint32_t dst, const void* src) {
    asm volatile("cp.async.cg.shared.global [%0], [%1], 16;" :: "r"(dst), "l"(src));
}

__device__ __forceinline__ uint32_t f2tf32(uint32_t bits) {
    uint32_t o;
    asm("cvt.rna.tf32.f32 %0, %1;" : "=r"(o) : "f"(__uint_as_float(bits)));
    return o;
}

__device__ __forceinline__ void ldsm_x4(uint32_t& r0, uint32_t& r1,
                                        uint32_t& r2, uint32_t& r3, uint32_t addr) {
    asm volatile("ldmatrix.sync.aligned.m8n8.x4.shared.b16 {%0,%1,%2,%3}, [%4];"
                 : "=r"(r0), "=r"(r1), "=r"(r2), "=r"(r3) : "r"(addr));
}

__device__ __forceinline__ void mma_tf32(float& c0, float& c1, float& c2, float& c3,
                                         uint32_t a0, uint32_t a1, uint32_t a2,
                                         uint32_t a3, uint32_t b0, uint32_t b1) {
    asm volatile(
        "mma.sync.aligned.m16n8k8.row.col.f32.tf32.tf32.f32 "
        "{%0,%1,%2,%3}, {%4,%5,%6,%7}, {%8,%9}, {%0,%1,%2,%3};"
        : "+f"(c0), "+f"(c1), "+f"(c2), "+f"(c3)
        : "r"(a0), "r"(a1), "r"(a2), "r"(a3), "r"(b0), "r"(b1));
}

__global__ void __launch_bounds__(NTHREADS, 1)
qkv_tf32_kernel(const float* __restrict__ A, const float* __restrict__ B,
                float* __restrict__ O) {
    extern __shared__ __align__(1024) char smem[];
    const uint32_t sbase = smem_u32(smem);
    const int tid = threadIdx.x;
    const int wid = tid >> 5;
    const int lid = tid & 31;
    const int wr = wid & 3;    // warp row: m-offset wr*64
    const int wc = wid >> 2;   // warp col: n-offset wc*32

    // Panel-swizzled tile mapping (8 m-tiles fast, n slow) for L2 reuse.
    const int bid = blockIdx.x;
    const int panel = bid / (PANEL_M * N_TILES);
    const int rr = bid % (PANEL_M * N_TILES);
    const int mt = panel * PANEL_M + (rr % PANEL_M);
    const int nt = rr / PANEL_M;
    const long m0 = (long)mt * BM;
    const long n0 = (long)nt * BN;

    // ---------------- cp.async load slots ----------------
    // A: 2048 16B chunks / 512 threads = 4 each; B: 1024 / 512 = 2 each.
    const float* aSrc[4];
    uint32_t aDst[4];
    #pragma unroll
    for (int c = 0; c < 4; c++) {
        int idx = c * NTHREADS + tid;
        int row = idx >> 3, cb = idx & 7;
        aSrc[c] = A + (m0 + row) * (long)KDIM + cb * 4;
        uint32_t bo = (uint32_t)(row * 128 + cb * 16);
        aDst[c] = bo ^ ((bo >> 3) & 0x70);
    }
    const float* bSrc[2];
    uint32_t bDst[2];
    #pragma unroll
    for (int c = 0; c < 2; c++) {
        int idx = c * NTHREADS + tid;
        int row = idx >> 3, cb = idx & 7;
        bSrc[c] = B + (n0 + row) * (long)KDIM + cb * 4;
        uint32_t bo = (uint32_t)(row * 128 + cb * 16);
        bDst[c] = A_BYTES + (bo ^ ((bo >> 3) & 0x70));
    }

    // ---------------- ldmatrix address components ----------------
    // A fragments (m16n8k8 row-major): x4 covers one m16 tile, one k-step.
    //   lane -> row R+(l&15), 16B-col select ((l>>4)&1).
    const uint32_t aRowOff = (uint32_t)((wr * 64 + (lid & 15)) * 128);
    const uint32_t aSwz = (uint32_t)((lid & 7) << 4);
    const uint32_t aHi = (uint32_t)(((lid >> 4) & 1) * 16);
    // B fragments (col-major = our [n][k] layout): x4 covers 2 n8 tiles, 1 k-step.
    //   lanes 0-7/8-15 -> n-tile pj rows, khalf 0/1; lanes 16-31 -> n-tile pj+1.
    const uint32_t bRowOff =
        (uint32_t)(A_BYTES + (wc * 32 + (lid & 7) + ((lid >> 4) & 1) * 8) * 128);
    const uint32_t bSwz = (uint32_t)((lid & 7) << 4);
    const uint32_t bHi = (uint32_t)(((lid >> 3) & 1) * 16);

    float acc[4][4][4];
    #pragma unroll
    for (int mi = 0; mi < 4; mi++)
        #pragma unroll
        for (int ni = 0; ni < 4; ni++)
            #pragma unroll
            for (int q = 0; q < 4; q++) acc[mi][ni][q] = 0.0f;

    // ---------------- prologue: fill stages 0,1 ----------------
    #pragma unroll
    for (int t = 0; t < STAGES - 1; t++) {
        uint32_t sb = sbase + t * STAGE_BYTES;
        #pragma unroll
        for (int c = 0; c < 4; c++) cpa16(sb + aDst[c], aSrc[c] + t * BK);
        #pragma unroll
        for (int c = 0; c < 2; c++) cpa16(sb + bDst[c], bSrc[c] + t * BK);
        asm volatile("cp.async.commit_group;");
    }

    // ---------------- main loop ----------------
    #pragma unroll 1
    for (int t = 0; t < KTILES; t++) {
        // Guard stage (t+2)%3 reuse against iter t-1's readers.
        __syncthreads();

        const int tf = t + STAGES - 1;
        if (tf < KTILES) {
            uint32_t sb = sbase + (tf % STAGES) * STAGE_BYTES;
            #pragma unroll
            for (int c = 0; c < 4; c++) cpa16(sb + aDst[c], aSrc[c] + tf * BK);
            #pragma unroll
            for (int c = 0; c < 2; c++) cpa16(sb + bDst[c], bSrc[c] + tf * BK);
        }
        asm volatile("cp.async.commit_group;");
        asm volatile("cp.async.wait_group 2;");  // groups <= t complete
        __syncthreads();

        const uint32_t sb = sbase + (t % STAGES) * STAGE_BYTES;

        #pragma unroll
        for (int ks = 0; ks < 4; ks++) {
            // B fragments: 2 ldmatrix.x4 -> b[4][2]
            uint32_t b[4][2];
            {
                const uint32_t xB = ((uint32_t)(ks * 32) | bHi) ^ bSwz;
                uint32_t q0, q1, q2, q3;
                ldsm_x4(q0, q1, q2, q3, sb + bRowOff + xB);
                b[0][0] = f2tf32(q0); b[0][1] = f2tf32(q1);
                b[1][0] = f2tf32(q2); b[1][1] = f2tf32(q3);
                ldsm_x4(q0, q1, q2, q3, sb + bRowOff + 2048 + xB);
                b[2][0] = f2tf32(q0); b[2][1] = f2tf32(q1);
                b[3][0] = f2tf32(q2); b[3][1] = f2tf32(q3);
            }
            // A fragments + MMAs per m-tile
            const uint32_t xA = ((uint32_t)(ks * 32) | aHi) ^ aSwz;
            #pragma unroll
            for (int mi = 0; mi < 4; mi++) {
                uint32_t a0, a1, a2, a3;
                ldsm_x4(a0, a1, a2, a3, sb + aRowOff + mi * 2048 + xA);
                a0 = f2tf32(a0); a1 = f2tf32(a1);
                a2 = f2tf32(a2); a3 = f2tf32(a3);
                #pragma unroll
                for (int ni = 0; ni < 4; ni++)
                    mma_tf32(acc[mi][ni][0], acc[mi][ni][1],
                             acc[mi][ni][2], acc[mi][ni][3],
                             a0, a1, a2, a3, b[ni][0], b[ni][1]);
            }
        }
    }

    // ---------------- epilogue: direct STG.64 ----------------
    // c0,c1 = (row g, cols 2*tig..2*tig+1); c2,c3 = (row g+8, same cols).
    {
        const int g = lid >> 2;
        const int tig = lid & 3;
        const long sec = n0 >> 12;                 // q/k/v section (BN | 4096)
        const long colbase = (n0 & 4095) + wc * 32 + tig * 2;
        float* Ob = O + sec * ((long)MDIM * 4096);
        #pragma unroll
        for (int mi = 0; mi < 4; mi++) {
            const long r = m0 + wr * 64 + mi * 16 + g;
            float* p0 = Ob + r * 4096 + colbase;
            float* p1 = p0 + 8 * 4096;
            #pragma unroll
            for (int ni = 0; ni < 4; ni++) {
                *reinterpret_cast<float2*>(p0 + ni * 8) =
                    make_float2(acc[mi][ni][0], acc[mi][ni][1]);
                *reinterpret_cast<float2*>(p1 + ni * 8) =
                    make_float2(acc[mi][ni][2], acc[mi][ni][3]);
            }
        }
    }
}

extern "C" void kernel_launch(void* const* d_in, const int* in_sizes, int n_in,
                              void* d_out, int out_size) {
    (void)in_sizes; (void)n_in; (void)out_size;
    const float* hs = (const float*)d_in[0];   // hidden_states [4,4096,4096]
    const float* w  = (const float*)d_in[1];   // qkv_proj [12288,4096]
    // d_in[2] = position_ids — RoPE is an identity stub; unused.
    float* out = (float*)d_out;

    cudaFuncSetAttribute(qkv_tf32_kernel,
                         cudaFuncAttributeMaxDynamicSharedMemorySize, SMEM_TOTAL);
    qkv_tf32_kernel<<<M_TILES * N_TILES, NTHREADS, SMEM_TOTAL>>>(hs, w, out);
}

// round 5
// speedup vs baseline: 1.2916x; 1.2916x over previous
#include <cuda_runtime.h>
#include <cstdint>

// ============================================================================
// QKV projection as one tf32 mma.sync GEMM (baseline PTX; tcgen05 rejected by
// this toolchain's .target sm_103):
//   C[16384, 12288] = A[16384,4096] @ B[12288,4096]^T
// A = hidden_states (row-major), B = qkv_proj (row-major), RoPE = identity.
// Output: 3 column sections of C -> q|k|v concatenated fp32 regions.
//
// R4 changes vs R3 (9324us, tensor 58% / fma 15% / alu 24%):
//  - no cvt.rna.tf32: feed raw fp32 bits to tf32 MMA (HW truncates mantissa)
//  - 4-stage cp.async pipeline (192KB smem), wait_group 3
//  - incremental global pointers + rotating smem stage bases (kill IMADs)
// ============================================================================

static constexpr int MDIM = 16384;
static constexpr int NDIM = 12288;
static constexpr int KDIM = 4096;

static constexpr int BM = 256;
static constexpr int BN = 128;
static constexpr int BK = 32;                  // 32 fp32 = 128 B row
static constexpr int KTILES = KDIM / BK;       // 128
static constexpr int STAGES = 4;
static constexpr int A_BYTES = BM * BK * 4;    // 32 KB
static constexpr int B_BYTES = BN * BK * 4;    // 16 KB
static constexpr int STAGE_BYTES = A_BYTES + B_BYTES;      // 48 KB
static constexpr int SMEM_TOTAL = STAGES * STAGE_BYTES;    // 192 KB
static constexpr int M_TILES = MDIM / BM;      // 64
static constexpr int N_TILES = NDIM / BN;      // 96
static constexpr int PANEL_M = 8;              // L2 rasterization panel
static constexpr int NTHREADS = 512;

__device__ __forceinline__ uint32_t smem_u32(const void* p) {
    uint32_t a;
    asm("{ .reg .u64 t; cvta.to.shared.u64 t, %1; cvt.u32.u64 %0, t; }"
        : "=r"(a) : "l"(p));
    return a;
}

__device__ __forceinline__ void cpa16(uint32_t dst, const void* src) {
    asm volatile("cp.async.cg.shared.global [%0], [%1], 16;" :: "r"(dst), "l"(src));
}

__device__ __forceinline__ void ldsm_x4(uint32_t& r0, uint32_t& r1,
                                        uint32_t& r2, uint32_t& r3, uint32_t addr) {
    asm volatile("ldmatrix.sync.aligned.m8n8.x4.shared.b16 {%0,%1,%2,%3}, [%4];"
                 : "=r"(r0), "=r"(r1), "=r"(r2), "=r"(r3) : "r"(addr));
}

__device__ __forceinline__ void mma_tf32(float& c0, float& c1, float& c2, float& c3,
                                         uint32_t a0, uint32_t a1, uint32_t a2,
                                         uint32_t a3, uint32_t b0, uint32_t b1) {
    asm volatile(
        "mma.sync.aligned.m16n8k8.row.col.f32.tf32.tf32.f32 "
        "{%0,%1,%2,%3}, {%4,%5,%6,%7}, {%8,%9}, {%0,%1,%2,%3};"
        : "+f"(c0), "+f"(c1), "+f"(c2), "+f"(c3)
        : "r"(a0), "r"(a1), "r"(a2), "r"(a3), "r"(b0), "r"(b1));
}

__global__ void __launch_bounds__(NTHREADS, 1)
qkv_tf32_kernel(const float* __restrict__ A, const float* __restrict__ B,
                float* __restrict__ O) {
    extern __shared__ __align__(1024) char smem[];
    const uint32_t sbase = smem_u32(smem);
    const int tid = threadIdx.x;
    const int wid = tid >> 5;
    const int lid = tid & 31;
    const int wr = wid & 3;    // warp row: m-offset wr*64
    const int wc = wid >> 2;   // warp col: n-offset wc*32

    // Panel-swizzled tile mapping (8 m-tiles fast, n slow) for L2 reuse.
    const int bid = blockIdx.x;
    const int panel = bid / (PANEL_M * N_TILES);
    const int rr = bid % (PANEL_M * N_TILES);
    const int mt = panel * PANEL_M + (rr % PANEL_M);
    const int nt = rr / PANEL_M;
    const long m0 = (long)mt * BM;
    const long n0 = (long)nt * BN;

    // ---------------- cp.async load slots (incremental pointers) ----------
    // A: 2048 16B chunks / 512 threads = 4 each; B: 1024 / 512 = 2 each.
    const float* aP[4];
    uint32_t aDst[4];
    #pragma unroll
    for (int c = 0; c < 4; c++) {
        int idx = c * NTHREADS + tid;
        int row = idx >> 3, cb = idx & 7;
        aP[c] = A + (m0 + row) * (long)KDIM + cb * 4;
        uint32_t bo = (uint32_t)(row * 128 + cb * 16);
        aDst[c] = bo ^ ((bo >> 3) & 0x70);
    }
    const float* bP[2];
    uint32_t bDst[2];
    #pragma unroll
    for (int c = 0; c < 2; c++) {
        int idx = c * NTHREADS + tid;
        int row = idx >> 3, cb = idx & 7;
        bP[c] = B + (n0 + row) * (long)KDIM + cb * 4;
        uint32_t bo = (uint32_t)(row * 128 + cb * 16);
        bDst[c] = A_BYTES + (bo ^ ((bo >> 3) & 0x70));
    }

    // ---------------- ldmatrix address components ----------------
    const uint32_t aRowOff = (uint32_t)((wr * 64 + (lid & 15)) * 128);
    const uint32_t aSwz = (uint32_t)((lid & 7) << 4);
    const uint32_t aHi = (uint32_t)(((lid >> 4) & 1) * 16);
    const uint32_t bRowOff =
        (uint32_t)(A_BYTES + (wc * 32 + (lid & 7) + ((lid >> 4) & 1) * 8) * 128);
    const uint32_t bSwz = (uint32_t)((lid & 7) << 4);
    const uint32_t bHi = (uint32_t)(((lid >> 3) & 1) * 16);

    float acc[4][4][4];
    #pragma unroll
    for (int mi = 0; mi < 4; mi++)
        #pragma unroll
        for (int ni = 0; ni < 4; ni++)
            #pragma unroll
            for (int q = 0; q < 4; q++) acc[mi][ni][q] = 0.0f;

    // ---------------- prologue: fill stages 0..2 ----------------
    #pragma unroll
    for (int t = 0; t < STAGES - 1; t++) {
        uint32_t sb = sbase + t * STAGE_BYTES;
        #pragma unroll
        for (int c = 0; c < 4; c++) { cpa16(sb + aDst[c], aP[c]); aP[c] += BK; }
        #pragma unroll
        for (int c = 0; c < 2; c++) { cpa16(sb + bDst[c], bP[c]); bP[c] += BK; }
        asm volatile("cp.async.commit_group;");
    }

    // Rotating stage bases: wrBase = stage being prefetched, rdBase = stage read.
    uint32_t wrBase = sbase + (STAGES - 1) * STAGE_BYTES;
    uint32_t rdBase = sbase;

    // ---------------- main loop ----------------
    #pragma unroll 1
    for (int t = 0; t < KTILES; t++) {
        // Guard stage reuse: wrBase == stage read at iter t-1 (distance 4).
        __syncthreads();

        if (t < KTILES - (STAGES - 1)) {
            #pragma unroll
            for (int c = 0; c < 4; c++) { cpa16(wrBase + aDst[c], aP[c]); aP[c] += BK; }
            #pragma unroll
            for (int c = 0; c < 2; c++) { cpa16(wrBase + bDst[c], bP[c]); bP[c] += BK; }
        }
        asm volatile("cp.async.commit_group;");
        asm volatile("cp.async.wait_group %0;" :: "n"(STAGES - 1));  // tile t done
        __syncthreads();

        const uint32_t sb = rdBase;

        #pragma unroll
        for (int ks = 0; ks < 4; ks++) {
            // B fragments: 2 ldmatrix.x4 -> b[4][2] (raw fp32 bits as tf32)
            uint32_t b[4][2];
            {
                const uint32_t xB = ((uint32_t)(ks * 32) | bHi) ^ bSwz;
                ldsm_x4(b[0][0], b[0][1], b[1][0], b[1][1], sb + bRowOff + xB);
                ldsm_x4(b[2][0], b[2][1], b[3][0], b[3][1], sb + bRowOff + 2048 + xB);
            }
            const uint32_t xA = ((uint32_t)(ks * 32) | aHi) ^ aSwz;
            #pragma unroll
            for (int mi = 0; mi < 4; mi++) {
                uint32_t a0, a1, a2, a3;
                ldsm_x4(a0, a1, a2, a3, sb + aRowOff + mi * 2048 + xA);
                #pragma unroll
                for (int ni = 0; ni < 4; ni++)
                    mma_tf32(acc[mi][ni][0], acc[mi][ni][1],
                             acc[mi][ni][2], acc[mi][ni][3],
                             a0, a1, a2, a3, b[ni][0], b[ni][1]);
            }
        }

        // Rotate stage bases (no modulo).
        wrBase = rdBase;
        rdBase += STAGE_BYTES;
        if (rdBase == sbase + STAGES * STAGE_BYTES) rdBase = sbase;
    }

    // ---------------- epilogue: direct STG.64 ----------------
    {
        const int g = lid >> 2;
        const int tig = lid & 3;
        const long sec = n0 >> 12;                 // q/k/v section (BN | 4096)
        const long colbase = (n0 & 4095) + wc * 32 + tig * 2;
        float* Ob = O + sec * ((long)MDIM * 4096);
        #pragma unroll
        for (int mi = 0; mi < 4; mi++) {
            const long r = m0 + wr * 64 + mi * 16 + g;
            float* p0 = Ob + r * 4096 + colbase;
            float* p1 = p0 + 8 * 4096;
            #pragma unroll
            for (int ni = 0; ni < 4; ni++) {
                *reinterpret_cast<float2*>(p0 + ni * 8) =
                    make_float2(acc[mi][ni][0], acc[mi][ni][1]);
                *reinterpret_cast<float2*>(p1 + ni * 8) =
                    make_float2(acc[mi][ni][2], acc[mi][ni][3]);
            }
        }
    }
}

extern "C" void kernel_launch(void* const* d_in, const int* in_sizes, int n_in,
                              void* d_out, int out_size) {
    (void)in_sizes; (void)n_in; (void)out_size;
    const float* hs = (const float*)d_in[0];   // hidden_states [4,4096,4096]
    const float* w  = (const float*)d_in[1];   // qkv_proj [12288,4096]
    // d_in[2] = position_ids — RoPE is an identity stub; unused.
    float* out = (float*)d_out;

    cudaFuncSetAttribute(qkv_tf32_kernel,
                         cudaFuncAttributeMaxDynamicSharedMemorySize, SMEM_TOTAL);
    qkv_tf32_kernel<<<M_TILES * N_TILES, NTHREADS, SMEM_TOTAL>>>(hs, w, out);
}